// round 15
// baseline (speedup 1.0000x reference)
#include <cuda_runtime.h>

#ifndef M_PI_F
#define M_PI_F 3.14159265358979323846f
#endif

#define FDIM 512
#define NOUT 100
#define RB   8             // rows per task
#define WPB  4             // warps per block (128 threads)
#define GRID_MAX 1024      // 8192 tasks / (1024*4 warps) = exactly 2 tasks/warp

__device__ __forceinline__ ulonglong2 ldg_cs16(const void* p) {
    ulonglong2 v;
    asm("ld.global.cs.v2.u64 {%0,%1}, [%2];" : "=l"(v.x), "=l"(v.y) : "l"(p));
    return v;
}
// volatile: forbids the compiler from hoisting weights back into registers
__device__ __forceinline__ ulonglong2 lds16(unsigned a) {
    ulonglong2 v;
    asm volatile("ld.shared.v2.u64 {%0,%1}, [%2];" : "=l"(v.x), "=l"(v.y) : "r"(a));
    return v;
}
__device__ __forceinline__ unsigned long long ffma2(unsigned long long a,
                                                    unsigned long long b,
                                                    unsigned long long c) {
    unsigned long long d;
    asm("fma.rn.f32x2 %0, %1, %2, %3;" : "=l"(d) : "l"(a), "l"(b), "l"(c));
    return d;
}
__device__ __forceinline__ float f32x2_hsum(unsigned long long v) {
    float lo, hi;
    asm("mov.b64 {%0, %1}, %2;" : "=f"(lo), "=f"(hi) : "l"(v));
    return lo + hi;
}
__device__ __forceinline__ float fast_tanh(float x) {
    return 1.0f - 2.0f / (__expf(2.0f * x) + 1.0f);
}

// Occupancy-first redesign:
//  - pre_W in SMEM (6KB/block), read per row via volatile 16B LDS (+12 LDS/row)
//    -> frees 48 registers -> 96 regs drop to ~70 -> ~28 warps/SM (was 20)
//  - X prefetch: 2-row register double-buffer (ld.global.cs), distance 2 rows
//    (~940cyc at 28-warp pressure > 577cyc DRAM) -> no cp.async machinery
//  - grid 1024: every warp exactly 2 tasks, all blocks resident, balanced
__global__ __launch_bounds__(128, 7)
void qnet_fused_kernel(const float* __restrict__ X,
                       const float* __restrict__ preW,
                       const float* __restrict__ preB,
                       const float* __restrict__ qp,
                       const float* __restrict__ postW,
                       const float* __restrict__ postB,
                       float* __restrict__ out,
                       int B)
{
    __shared__ float wsm[3 * FDIM];   // 6KB

    const int tid  = threadIdx.x;
    const int wid  = tid >> 5;
    const int lane = tid & 31;

    // stage pre_W (once per block)
    {
        const float4* Wg = reinterpret_cast<const float4*>(preW);
        float4* ws4 = reinterpret_cast<float4*>(wsm);
        #pragma unroll
        for (int i = 0; i < 3; ++i) ws4[tid + 128 * i] = Wg[tid + 128 * i];
    }
    __syncthreads();

    const int n_tasks     = (B + RB - 1) / RB;
    const int warp_g      = blockIdx.x * WPB + wid;
    const int warp_stride = gridDim.x * WPB;
    if (warp_g >= n_tasks) return;
    const int n_my = (n_tasks - 1 - warp_g) / warp_stride + 1;

    const char* __restrict__ Xb = reinterpret_cast<const char*>(X) + lane * 16;

    ulonglong2 xb[2][4];   // 2-row register double buffer (32 regs)
    auto loadrow = [&](int buf, int i) {
        const int t   = warp_g + (i >> 3) * warp_stride;
        const int row = min(t * RB + (i & 7), B - 1);   // clamp: tail-safe
        const char* src = Xb + (size_t)row * (FDIM * 4);
        #pragma unroll
        for (int k = 0; k < 4; ++k) xb[buf][k] = ldg_cs16(src + 512 * k);
    };
    loadrow(0, 0); loadrow(1, 1);

    const unsigned waddr = (unsigned)__cvta_generic_to_shared(wsm) + lane * 16;

    const float pb0 = __ldg(preB + 0), pb1 = __ldg(preB + 1), pb2 = __ldg(preB + 2);
    float qw[6];
    #pragma unroll
    for (int j = 0; j < 6; ++j) qw[j] = __ldg(qp + 3 + j);

    const int grp  = lane >> 3;
    const int mr   = lane & 7;
    const int srcl = (mr & 3) << 3;

    const float4* __restrict__ pW4 = reinterpret_cast<const float4*>(postW);
    const float4* __restrict__ pB4 = reinterpret_cast<const float4*>(postB);

    for (int it = 0; it < n_my; ++it) {
        const int base = (warp_g + it * warp_stride) * RB;

        float c0a = 0.f, c1a = 0.f, c2a = 0.f;
        float c0b = 0.f, c1b = 0.f, c2b = 0.f;

        #pragma unroll
        for (int r = 0; r < RB; ++r) {
            const int bsel = r & 1;
            unsigned long long acc0 = 0, acc1 = 0, acc2 = 0;
            #pragma unroll
            for (int k = 0; k < 4; ++k) {
                const ulonglong2 xv = xb[bsel][k];
                const ulonglong2 w0 = lds16(waddr + 512 * k);
                const ulonglong2 w1 = lds16(waddr + 2048 + 512 * k);
                const ulonglong2 w2 = lds16(waddr + 4096 + 512 * k);
                acc0 = ffma2(xv.x, w0.x, acc0); acc0 = ffma2(xv.y, w0.y, acc0);
                acc1 = ffma2(xv.x, w1.x, acc1); acc1 = ffma2(xv.y, w1.y, acc1);
                acc2 = ffma2(xv.x, w2.x, acc2); acc2 = ffma2(xv.y, w2.y, acc2);
            }
            // refill the buffer just consumed with row i+2 (crosses task bounds)
            loadrow(bsel, it * RB + r + 2);

            float v0 = f32x2_hsum(acc0);
            float v1 = f32x2_hsum(acc1);
            float v2 = f32x2_hsum(acc2);

            v0 += __shfl_xor_sync(0xFFFFFFFFu, v0, 16);
            v1 += __shfl_xor_sync(0xFFFFFFFFu, v1, 16);
            v2 += __shfl_xor_sync(0xFFFFFFFFu, v2, 16);
            v0 += __shfl_xor_sync(0xFFFFFFFFu, v0, 8);
            v1 += __shfl_xor_sync(0xFFFFFFFFu, v1, 8);
            v2 += __shfl_xor_sync(0xFFFFFFFFu, v2, 8);

            const bool g = (grp == (r & 3));
            if (r < 4) {
                c0a = g ? v0 : c0a;  c1a = g ? v1 : c1a;  c2a = g ? v2 : c2a;
            } else {
                c0b = g ? v0 : c0b;  c1b = g ? v1 : c1b;  c2b = g ? v2 : c2b;
            }
        }

        #pragma unroll
        for (int off = 4; off > 0; off >>= 1) {
            c0a += __shfl_xor_sync(0xFFFFFFFFu, c0a, off);
            c1a += __shfl_xor_sync(0xFFFFFFFFu, c1a, off);
            c2a += __shfl_xor_sync(0xFFFFFFFFu, c2a, off);
            c0b += __shfl_xor_sync(0xFFFFFFFFu, c0b, off);
            c1b += __shfl_xor_sync(0xFFFFFFFFu, c1b, off);
            c2b += __shfl_xor_sync(0xFFFFFFFFu, c2b, off);
        }

        const float xa0 = __shfl_sync(0xFFFFFFFFu, c0a, srcl);
        const float xb0 = __shfl_sync(0xFFFFFFFFu, c0b, srcl);
        const float xa1 = __shfl_sync(0xFFFFFFFFu, c1a, srcl);
        const float xb1 = __shfl_sync(0xFFFFFFFFu, c1b, srcl);
        const float xa2 = __shfl_sync(0xFFFFFFFFu, c2a, srcl);
        const float xb2 = __shfl_sync(0xFFFFFFFFu, c2b, srcl);
        const float a0 = (mr < 4) ? xa0 : xb0;
        const float a1 = (mr < 4) ? xa1 : xb1;
        const float a2 = (mr < 4) ? xa2 : xb2;

        // ---- per-lane circuit (lane l&7 = row l&7) ----
        const float t0 = fast_tanh(a0 + pb0) * (M_PI_F * 0.5f);
        const float t1 = fast_tanh(a1 + pb1) * (M_PI_F * 0.5f);
        const float t2 = fast_tanh(a2 + pb2) * (M_PI_F * 0.5f);

        float s[8];
        const float inv_sqrt8 = 0.3535533905932738f;
        #pragma unroll
        for (int i = 0; i < 8; ++i) s[i] = inv_sqrt8;

        auto ry0 = [&](float th) {
            float sn, cs; __sincosf(th * 0.5f, &sn, &cs);
            #pragma unroll
            for (int i = 0; i < 4; ++i) {
                float a = s[i], b = s[i + 4];
                s[i]     = cs * a - sn * b;
                s[i + 4] = sn * a + cs * b;
            }
        };
        auto ry1 = [&](float th) {
            float sn, cs; __sincosf(th * 0.5f, &sn, &cs);
            #pragma unroll
            for (int g2 = 0; g2 < 2; ++g2)
                #pragma unroll
                for (int i = 0; i < 2; ++i) {
                    int lo = g2 * 4 + i;
                    float a = s[lo], b = s[lo + 2];
                    s[lo]     = cs * a - sn * b;
                    s[lo + 2] = sn * a + cs * b;
                }
        };
        auto ry2 = [&](float th) {
            float sn, cs; __sincosf(th * 0.5f, &sn, &cs);
            #pragma unroll
            for (int g2 = 0; g2 < 4; ++g2) {
                int lo = g2 * 2;
                float a = s[lo], b = s[lo + 1];
                s[lo]     = cs * a - sn * b;
                s[lo + 1] = sn * a + cs * b;
            }
        };

        ry0(t0); ry1(t1); ry2(t2);

        #pragma unroll
        for (int k = 0; k < 2; ++k) {
            float tmp;
            tmp = s[4]; s[4] = s[6]; s[6] = tmp;   // CNOT(0,1)
            tmp = s[5]; s[5] = s[7]; s[7] = tmp;
            tmp = s[2]; s[2] = s[3]; s[3] = tmp;   // CNOT(1,2)
            tmp = s[6]; s[6] = s[7]; s[7] = tmp;
            ry0(qw[3 * k + 0]);
            ry1(qw[3 * k + 1]);
            ry2(qw[3 * k + 2]);
        }

        float p[8];
        #pragma unroll
        for (int i = 0; i < 8; ++i) p[i] = s[i] * s[i];

        const float z0 = (p[0] + p[1] + p[2] + p[3]) - (p[4] + p[5] + p[6] + p[7]);
        const float z1 = (p[0] + p[1] + p[4] + p[5]) - (p[2] + p[3] + p[6] + p[7]);
        const float z2 = (p[0] + p[2] + p[4] + p[6]) - (p[1] + p[3] + p[5] + p[7]);

        // ---- epilogue: this task's rows x 25 float4, contiguous ----
        const int rows = min(RB, B - base);
        float4* __restrict__ out4 = reinterpret_cast<float4*>(out) + (size_t)base * 25;
        const int lim = rows * 25;
        #pragma unroll
        for (int i = 0; i < 7; ++i) {
            const int f4  = i * 32 + lane;      // 0..223 ; valid < 200
            const int row = f4 / 25;
            const int g2  = f4 - row * 25;
            const float zz0 = __shfl_sync(0xFFFFFFFFu, z0, row & 7);
            const float zz1 = __shfl_sync(0xFFFFFFFFu, z1, row & 7);
            const float zz2 = __shfl_sync(0xFFFFFFFFu, z2, row & 7);
            if (f4 < lim) {
                const float4 f0 = __ldg(pW4 + 3 * g2 + 0);
                const float4 f1 = __ldg(pW4 + 3 * g2 + 1);
                const float4 f2 = __ldg(pW4 + 3 * g2 + 2);
                const float4 bb = __ldg(pB4 + g2);
                float4 o;
                o.x = zz0 * f0.x + zz1 * f0.y + zz2 * f0.z + bb.x;
                o.y = zz0 * f0.w + zz1 * f1.x + zz2 * f1.y + bb.y;
                o.z = zz0 * f1.z + zz1 * f1.w + zz2 * f2.x + bb.z;
                o.w = zz0 * f2.y + zz1 * f2.z + zz2 * f2.w + bb.w;
                __stcs(out4 + f4, o);
            }
        }
    }
}

extern "C" void kernel_launch(void* const* d_in, const int* in_sizes, int n_in,
                              void* d_out, int out_size)
{
    const float* X     = (const float*)d_in[0]; // [B, 512]
    const float* preW  = (const float*)d_in[1]; // [3, 512]
    const float* preB  = (const float*)d_in[2]; // [3]
    const float* qp    = (const float*)d_in[3]; // [45]
    const float* postW = (const float*)d_in[4]; // [100, 3]
    const float* postB = (const float*)d_in[5]; // [100]
    float* out = (float*)d_out;                 // [B, 100]

    const int B = in_sizes[0] / FDIM;
    const int n_tasks = (B + RB - 1) / RB;
    int blocks = (n_tasks + WPB - 1) / WPB;
    if (blocks > GRID_MAX) blocks = GRID_MAX;

    qnet_fused_kernel<<<blocks, WPB * 32>>>(X, preW, preB, qp, postW, postB, out, B);
}

// round 16
// speedup vs baseline: 1.4987x; 1.4987x over previous
#include <cuda_runtime.h>

#ifndef M_PI_F
#define M_PI_F 3.14159265358979323846f
#endif

#define FDIM 512
#define NOUT 100
#define RB   8             // rows per task
#define WPB  4             // warps per block (128 threads)
#define STAGES 4
#define GRID_BLOCKS 740    // 148 SMs x 5 blocks: one balanced wave

__device__ __forceinline__ void cp_async16(unsigned int saddr, const void* gaddr) {
    asm volatile("cp.async.cg.shared.global [%0], [%1], 16;" :: "r"(saddr), "l"(gaddr));
}
__device__ __forceinline__ void cp_commit() {
    asm volatile("cp.async.commit_group;" ::: "memory");
}
template <int N>
__device__ __forceinline__ void cp_wait() {
    asm volatile("cp.async.wait_group %0;" :: "n"(N) : "memory");
}
__device__ __forceinline__ unsigned long long ffma2(unsigned long long a,
                                                    unsigned long long b,
                                                    unsigned long long c) {
    unsigned long long d;
    asm("fma.rn.f32x2 %0, %1, %2, %3;" : "=l"(d) : "l"(a), "l"(b), "l"(c));
    return d;
}
__device__ __forceinline__ float f32x2_hsum(unsigned long long v) {
    float lo, hi;
    asm("mov.b64 {%0, %1}, %2;" : "=f"(lo), "=f"(hi) : "l"(v));
    return lo + hi;
}
__device__ __forceinline__ float fast_tanh(float x) {
    return 1.0f - 2.0f / (__expf(2.0f * x) + 1.0f);
}

// R12 champion + task PAIRING: two 8-row dot subtasks share ONE circuit pass.
// Subtask 0's activations live in lanes 0-7/16-23, subtask 1's in 8-15/24-31;
// the per-lane circuit then covers 16 rows per pass (was 8), saving ~220
// instructions per pair. Ring, dot, reduction, epilogue identical to R12.
__global__ __launch_bounds__(128, 5)
void qnet_fused_kernel(const float* __restrict__ X,
                       const float* __restrict__ preW,
                       const float* __restrict__ preB,
                       const float* __restrict__ qp,
                       const float* __restrict__ postW,
                       const float* __restrict__ postB,
                       float* __restrict__ out,
                       int B)
{
    __shared__ float4 xring[WPB][STAGES][128];   // 32KB static

    const int tid  = threadIdx.x;
    const int wid  = tid >> 5;
    const int lane = tid & 31;

    const int n_tasks     = (B + RB - 1) / RB;
    const int warp_g      = blockIdx.x * WPB + wid;
    const int warp_stride = gridDim.x * WPB;
    if (warp_g >= n_tasks) return;
    const int n_my = (n_tasks - 1 - warp_g) / warp_stride + 1;

    const float4* __restrict__ X4 = reinterpret_cast<const float4*>(X);

    auto row_of = [&](int i) -> int {
        const int t = warp_g + (i >> 3) * warp_stride;
        return min(t * RB + (i & 7), B - 1);
    };
    auto issue = [&](int i) {
        const float4* __restrict__ src = X4 + (size_t)row_of(i) * 128;
        float4* dst = &xring[wid][i & (STAGES - 1)][0];
        #pragma unroll
        for (int k = 0; k < 4; ++k) {
            unsigned int sa = (unsigned int)__cvta_generic_to_shared(dst + lane + 32 * k);
            cp_async16(sa, src + lane + 32 * k);
        }
        cp_commit();
    };

    issue(0); issue(1); issue(2); issue(3);

    // ---- once-per-warp prolog ----
    const ulonglong2* __restrict__ Wp = reinterpret_cast<const ulonglong2*>(preW);
    unsigned long long w0p[8], w1p[8], w2p[8];
    #pragma unroll
    for (int k = 0; k < 4; ++k) {
        const int i = lane + 32 * k;
        ulonglong2 q0 = __ldg(Wp + i);
        ulonglong2 q1 = __ldg(Wp + 128 + i);
        ulonglong2 q2 = __ldg(Wp + 256 + i);
        w0p[2 * k] = q0.x; w0p[2 * k + 1] = q0.y;
        w1p[2 * k] = q1.x; w1p[2 * k + 1] = q1.y;
        w2p[2 * k] = q2.x; w2p[2 * k + 1] = q2.y;
    }
    const float pb0 = __ldg(preB + 0), pb1 = __ldg(preB + 1), pb2 = __ldg(preB + 2);
    float qw[6];
    #pragma unroll
    for (int j = 0; j < 6; ++j) qw[j] = __ldg(qp + 3 + j);

    const int grp  = lane >> 3;
    const int mr   = lane & 7;
    const int srcl = (mr & 3) << 3;
    const int half = (lane >> 3) & 1;   // which subtask of a pair this lane owns

    const float4* __restrict__ pW4 = reinterpret_cast<const float4*>(postW);
    const float4* __restrict__ pB4 = reinterpret_cast<const float4*>(postB);

    // 8-row dot subtask: full R12 loop, leaves row (l&7)'s sums in every lane
    auto subtask = [&](int it, bool isLast, float& a0, float& a1, float& a2) {
        float c0a = 0.f, c1a = 0.f, c2a = 0.f;
        float c0b = 0.f, c1b = 0.f, c2b = 0.f;
        #pragma unroll
        for (int r = 0; r < RB; ++r) {
            const int i = it * RB + r;
            if (!isLast || r < 5)  cp_wait<3>();
            else if (r == 5)       cp_wait<2>();
            else if (r == 6)       cp_wait<1>();
            else                   cp_wait<0>();

            const ulonglong2* xs = reinterpret_cast<const ulonglong2*>(
                &xring[wid][i & (STAGES - 1)][0]);
            unsigned long long acc0 = 0, acc1 = 0, acc2 = 0;
            #pragma unroll
            for (int k = 0; k < 4; ++k) {
                const ulonglong2 xv = xs[lane + 32 * k];
                acc0 = ffma2(xv.x, w0p[2 * k],     acc0);
                acc0 = ffma2(xv.y, w0p[2 * k + 1], acc0);
                acc1 = ffma2(xv.x, w1p[2 * k],     acc1);
                acc1 = ffma2(xv.y, w1p[2 * k + 1], acc1);
                acc2 = ffma2(xv.x, w2p[2 * k],     acc2);
                acc2 = ffma2(xv.y, w2p[2 * k + 1], acc2);
            }
            if (!isLast || r < 4) issue(i + 4);   // continuous across tasks

            float v0 = f32x2_hsum(acc0);
            float v1 = f32x2_hsum(acc1);
            float v2 = f32x2_hsum(acc2);

            v0 += __shfl_xor_sync(0xFFFFFFFFu, v0, 16);
            v1 += __shfl_xor_sync(0xFFFFFFFFu, v1, 16);
            v2 += __shfl_xor_sync(0xFFFFFFFFu, v2, 16);
            v0 += __shfl_xor_sync(0xFFFFFFFFu, v0, 8);
            v1 += __shfl_xor_sync(0xFFFFFFFFu, v1, 8);
            v2 += __shfl_xor_sync(0xFFFFFFFFu, v2, 8);

            const bool g = (grp == (r & 3));
            if (r < 4) {
                c0a = g ? v0 : c0a;  c1a = g ? v1 : c1a;  c2a = g ? v2 : c2a;
            } else {
                c0b = g ? v0 : c0b;  c1b = g ? v1 : c1b;  c2b = g ? v2 : c2b;
            }
        }
        #pragma unroll
        for (int off = 4; off > 0; off >>= 1) {
            c0a += __shfl_xor_sync(0xFFFFFFFFu, c0a, off);
            c1a += __shfl_xor_sync(0xFFFFFFFFu, c1a, off);
            c2a += __shfl_xor_sync(0xFFFFFFFFu, c2a, off);
            c0b += __shfl_xor_sync(0xFFFFFFFFu, c0b, off);
            c1b += __shfl_xor_sync(0xFFFFFFFFu, c1b, off);
            c2b += __shfl_xor_sync(0xFFFFFFFFu, c2b, off);
        }
        const float xa0 = __shfl_sync(0xFFFFFFFFu, c0a, srcl);
        const float xb0 = __shfl_sync(0xFFFFFFFFu, c0b, srcl);
        const float xa1 = __shfl_sync(0xFFFFFFFFu, c1a, srcl);
        const float xb1 = __shfl_sync(0xFFFFFFFFu, c1b, srcl);
        const float xa2 = __shfl_sync(0xFFFFFFFFu, c2a, srcl);
        const float xb2 = __shfl_sync(0xFFFFFFFFu, c2b, srcl);
        a0 = (mr < 4) ? xa0 : xb0;
        a1 = (mr < 4) ? xa1 : xb1;
        a2 = (mr < 4) ? xa2 : xb2;
    };

    // circuit: lane's (A0,A1,A2) -> (z0,z1,z2)
    auto circuit = [&](float A0, float A1, float A2,
                       float& z0, float& z1, float& z2) {
        const float t0 = fast_tanh(A0 + pb0) * (M_PI_F * 0.5f);
        const float t1 = fast_tanh(A1 + pb1) * (M_PI_F * 0.5f);
        const float t2 = fast_tanh(A2 + pb2) * (M_PI_F * 0.5f);
        float s[8];
        const float inv_sqrt8 = 0.3535533905932738f;
        #pragma unroll
        for (int i = 0; i < 8; ++i) s[i] = inv_sqrt8;
        auto ry0 = [&](float th) {
            float sn, cs; __sincosf(th * 0.5f, &sn, &cs);
            #pragma unroll
            for (int i = 0; i < 4; ++i) {
                float a = s[i], b = s[i + 4];
                s[i] = cs * a - sn * b;  s[i + 4] = sn * a + cs * b;
            }
        };
        auto ry1 = [&](float th) {
            float sn, cs; __sincosf(th * 0.5f, &sn, &cs);
            #pragma unroll
            for (int g2 = 0; g2 < 2; ++g2)
                #pragma unroll
                for (int i = 0; i < 2; ++i) {
                    int lo = g2 * 4 + i;
                    float a = s[lo], b = s[lo + 2];
                    s[lo] = cs * a - sn * b;  s[lo + 2] = sn * a + cs * b;
                }
        };
        auto ry2 = [&](float th) {
            float sn, cs; __sincosf(th * 0.5f, &sn, &cs);
            #pragma unroll
            for (int g2 = 0; g2 < 4; ++g2) {
                int lo = g2 * 2;
                float a = s[lo], b = s[lo + 1];
                s[lo] = cs * a - sn * b;  s[lo + 1] = sn * a + cs * b;
            }
        };
        ry0(t0); ry1(t1); ry2(t2);
        #pragma unroll
        for (int k = 0; k < 2; ++k) {
            float tmp;
            tmp = s[4]; s[4] = s[6]; s[6] = tmp;   // CNOT(0,1)
            tmp = s[5]; s[5] = s[7]; s[7] = tmp;
            tmp = s[2]; s[2] = s[3]; s[3] = tmp;   // CNOT(1,2)
            tmp = s[6]; s[6] = s[7]; s[7] = tmp;
            ry0(qw[3 * k + 0]); ry1(qw[3 * k + 1]); ry2(qw[3 * k + 2]);
        }
        float p[8];
        #pragma unroll
        for (int i = 0; i < 8; ++i) p[i] = s[i] * s[i];
        z0 = (p[0] + p[1] + p[2] + p[3]) - (p[4] + p[5] + p[6] + p[7]);
        z1 = (p[0] + p[1] + p[4] + p[5]) - (p[2] + p[3] + p[6] + p[7]);
        z2 = (p[0] + p[2] + p[4] + p[6]) - (p[1] + p[3] + p[5] + p[7]);
    };

    // epilogue for one 8-row task; z for local row r lives in lane (srcbase+r)
    auto epilogue = [&](int task, int srcbase, float z0, float z1, float z2) {
        const int base = task * RB;
        const int rows = min(RB, B - base);
        float4* __restrict__ out4 = reinterpret_cast<float4*>(out) + (size_t)base * 25;
        const int lim = rows * 25;
        #pragma unroll
        for (int i = 0; i < 7; ++i) {
            const int f4  = i * 32 + lane;
            const int row = f4 / 25;
            const int g2  = f4 - row * 25;
            const float zz0 = __shfl_sync(0xFFFFFFFFu, z0, srcbase + (row & 7));
            const float zz1 = __shfl_sync(0xFFFFFFFFu, z1, srcbase + (row & 7));
            const float zz2 = __shfl_sync(0xFFFFFFFFu, z2, srcbase + (row & 7));
            if (f4 < lim) {
                const float4 f0 = __ldg(pW4 + 3 * g2 + 0);
                const float4 f1 = __ldg(pW4 + 3 * g2 + 1);
                const float4 f2 = __ldg(pW4 + 3 * g2 + 2);
                const float4 bb = __ldg(pB4 + g2);
                float4 o;
                o.x = zz0 * f0.x + zz1 * f0.y + zz2 * f0.z + bb.x;
                o.y = zz0 * f0.w + zz1 * f1.x + zz2 * f1.y + bb.y;
                o.z = zz0 * f1.z + zz1 * f1.w + zz2 * f2.x + bb.z;
                o.w = zz0 * f2.y + zz1 * f2.z + zz2 * f2.w + bb.w;
                __stcs(out4 + f4, o);
            }
        }
    };

    int it = 0;
    const int npairs = n_my >> 1;
    for (int pp = 0; pp < npairs; ++pp, it += 2) {
        float A0 = 0.f, A1 = 0.f, A2 = 0.f;
        float a0, a1, a2;
        subtask(it, false, a0, a1, a2);
        if (half == 0) { A0 = a0; A1 = a1; A2 = a2; }
        subtask(it + 1, (it + 1 == n_my - 1), a0, a1, a2);
        if (half == 1) { A0 = a0; A1 = a1; A2 = a2; }

        float z0, z1, z2;
        circuit(A0, A1, A2, z0, z1, z2);   // ONE circuit covers 16 rows

        const int t0g = warp_g + it * warp_stride;
        const int t1g = warp_g + (it + 1) * warp_stride;
        epilogue(t0g, 0, z0, z1, z2);      // subtask 0 rows: lanes 0-7
        epilogue(t1g, 8, z0, z1, z2);      // subtask 1 rows: lanes 8-15
    }
    if (n_my & 1) {
        float a0, a1, a2;
        subtask(it, true, a0, a1, a2);
        float z0, z1, z2;
        circuit(a0, a1, a2, z0, z1, z2);
        epilogue(warp_g + it * warp_stride, 0, z0, z1, z2);
    }
}

extern "C" void kernel_launch(void* const* d_in, const int* in_sizes, int n_in,
                              void* d_out, int out_size)
{
    const float* X     = (const float*)d_in[0]; // [B, 512]
    const float* preW  = (const float*)d_in[1]; // [3, 512]
    const float* preB  = (const float*)d_in[2]; // [3]
    const float* qp    = (const float*)d_in[3]; // [45]
    const float* postW = (const float*)d_in[4]; // [100, 3]
    const float* postB = (const float*)d_in[5]; // [100]
    float* out = (float*)d_out;                 // [B, 100]

    const int B = in_sizes[0] / FDIM;
    const int n_tasks = (B + RB - 1) / RB;
    int blocks = (n_tasks + WPB - 1) / WPB;
    if (blocks > GRID_BLOCKS) blocks = GRID_BLOCKS;

    qnet_fused_kernel<<<blocks, WPB * 32>>>(X, preW, preB, qp, postW, postB, out, B);
}